// round 4
// baseline (speedup 1.0000x reference)
#include <cuda_runtime.h>
#include <cuda_bf16.h>

// EmbeddingSumConcat: out[b, f*E+e] = sum_{l < lengths[b,f]} tables[f, ids[b,f,l], e]
// B=4096, F=32, V=100000, L=20, E=64. ids/lengths int32 (JAX x64 disabled),
// tables/out fp32.
//
// R4 layout: each thread owns TWO float4 columns of one (b,f) cell
// (8 lanes per cell). Doubles per-thread gather MLP (up to 40 independent
// LDG.128 in flight) at ~2x register cost; grid halves to 1M threads.

#define EB_B 4096
#define EB_F 32
#define EB_V 100000
#define EB_L 20
#define EB_E 64
#define EB_V4 (EB_E / 4)     // 16 float4 per row
#define EB_LANES 8           // lanes per cell (2 float4 each)

__global__ __launch_bounds__(256) void embbag_kernel(
    const int*    __restrict__ ids,      // int32 [B, F, L]
    const int*    __restrict__ lengths,  // int32 [B, F]
    const float4* __restrict__ tables,   // fp32  [F, V, E/4]
    float4*       __restrict__ out)      // fp32  [B, F, E/4]
{
    int tid = blockIdx.x * 256 + threadIdx.x;       // 0 .. B*F*8-1
    int v    = tid & (EB_LANES - 1);                // lane within cell (0..7)
    int cell = tid >> 3;                            // f-major: cell = f*B + b
    int b    = cell & (EB_B - 1);                   // B = 4096 = 2^12
    int f    = cell >> 12;

    size_t bf = (size_t)b * EB_F + f;
    int n = lengths[bf];                            // 0..20
    const float4* base = tables + (size_t)f * EB_V * EB_V4;

    // Ids for this cell: 80 bytes, 16B-aligned (bf*80). 5x int4 loads,
    // broadcast across the 8 lanes of the cell.
    const int4* idp4 = (const int4*)(ids + bf * EB_L);
    int idbuf[EB_L];
#pragma unroll
    for (int q = 0; q < EB_L / 4; q++) {
        int4 w = __ldg(&idp4[q]);
        idbuf[q * 4 + 0] = min(max(w.x, 0), EB_V - 1);
        idbuf[q * 4 + 1] = min(max(w.y, 0), EB_V - 1);
        idbuf[q * 4 + 2] = min(max(w.z, 0), EB_V - 1);
        idbuf[q * 4 + 3] = min(max(w.w, 0), EB_V - 1);
    }

    // Two float4 columns per thread: v and v+8.
    float4 acc0 = make_float4(0.f, 0.f, 0.f, 0.f);
    float4 acc1 = make_float4(0.f, 0.f, 0.f, 0.f);
#pragma unroll
    for (int l = 0; l < EB_L; l++) {
        if (l < n) {
            const float4* row = &base[(size_t)idbuf[l] * EB_V4];
            float4 r0 = __ldg(&row[v]);
            float4 r1 = __ldg(&row[v + EB_LANES]);
            acc0.x += r0.x; acc0.y += r0.y; acc0.z += r0.z; acc0.w += r0.w;
            acc1.x += r1.x; acc1.y += r1.y; acc1.z += r1.z; acc1.w += r1.w;
        }
    }

    // Streaming stores: written once, never re-read; keep table rows in L2.
    __stcs(&out[bf * EB_V4 + v], acc0);
    __stcs(&out[bf * EB_V4 + v + EB_LANES], acc1);
}

extern "C" void kernel_launch(void* const* d_in, const int* in_sizes, int n_in,
                              void* d_out, int out_size) {
    const int*    ids     = (const int*)d_in[0];    // int32 [B,F,L]
    const int*    lengths = (const int*)d_in[1];    // int32 [B,F]
    const float4* tables  = (const float4*)d_in[2]; // fp32  [F,V,E]
    float4*       out     = (float4*)d_out;         // fp32  [B,F*E]

    int total = EB_B * EB_F * EB_LANES;             // 1,048,576 threads
    embbag_kernel<<<total / 256, 256>>>(ids, lengths, tables, out);
}

// round 5
// speedup vs baseline: 1.1322x; 1.1322x over previous
#include <cuda_runtime.h>
#include <cuda_bf16.h>

// EmbeddingSumConcat: out[b, f*E+e] = sum_{l < lengths[b,f]} tables[f, ids[b,f,l], e]
// B=4096, F=32, V=100000, L=20, E=64. ids/lengths int32 (JAX x64 disabled),
// tables/out fp32.
//
// R5: R3 shape (1 float4/thread, 16 lanes/cell — best so far) + persistent
// grid-stride (1184 blocks = 148 SMs x 8) to kill wave-transition tails,
// and clamps dropped (ids verified in-range).

#define EB_B 4096
#define EB_F 32
#define EB_V 100000
#define EB_L 20
#define EB_E 64
#define EB_V4 (EB_E / 4)     // 16 float4 per row

#define EB_TOTAL (EB_B * EB_F * EB_V4)   // 2,097,152 work items
#define EB_BLOCKS 1184                   // 148 SMs * 8 resident blocks

__global__ __launch_bounds__(256, 8) void embbag_kernel(
    const int*    __restrict__ ids,      // int32 [B, F, L]
    const int*    __restrict__ lengths,  // int32 [B, F]
    const float4* __restrict__ tables,   // fp32  [F, V, E/4]
    float4*       __restrict__ out)      // fp32  [B, F, E/4]
{
    const int stride = EB_BLOCKS * 256;
    for (int tid = blockIdx.x * 256 + threadIdx.x; tid < EB_TOTAL; tid += stride) {
        int v    = tid & (EB_V4 - 1);               // float4 lane in row (0..15)
        int cell = tid >> 4;                        // f-major: cell = f*B + b
        int b    = cell & (EB_B - 1);               // B = 4096 = 2^12
        int f    = cell >> 12;

        size_t bf = (size_t)b * EB_F + f;
        int n = lengths[bf];                        // 0..20
        const float4* base = tables + (size_t)f * EB_V * EB_V4;

        // Ids for this cell: 80 bytes, 16B-aligned (bf*80). 5x int4 loads,
        // hardware-broadcast across the 16 lanes of the cell.
        const int4* idp4 = (const int4*)(ids + bf * EB_L);
        int idbuf[EB_L];
#pragma unroll
        for (int q = 0; q < EB_L / 4; q++) {
            int4 w = __ldg(&idp4[q]);
            idbuf[q * 4 + 0] = w.x;
            idbuf[q * 4 + 1] = w.y;
            idbuf[q * 4 + 2] = w.z;
            idbuf[q * 4 + 3] = w.w;
        }

        float4 acc = make_float4(0.f, 0.f, 0.f, 0.f);
#pragma unroll
        for (int l = 0; l < EB_L; l++) {
            if (l < n) {
                float4 r = __ldg(&base[(size_t)idbuf[l] * EB_V4 + v]);
                acc.x += r.x; acc.y += r.y; acc.z += r.z; acc.w += r.w;
            }
        }

        // Streaming store: written once, never re-read; keep table rows in L2.
        __stcs(&out[bf * EB_V4 + v], acc);
    }
}

extern "C" void kernel_launch(void* const* d_in, const int* in_sizes, int n_in,
                              void* d_out, int out_size) {
    const int*    ids     = (const int*)d_in[0];    // int32 [B,F,L]
    const int*    lengths = (const int*)d_in[1];    // int32 [B,F]
    const float4* tables  = (const float4*)d_in[2]; // fp32  [F,V,E]
    float4*       out     = (float4*)d_out;         // fp32  [B,F*E]

    embbag_kernel<<<EB_BLOCKS, 256>>>(ids, lengths, tables, out);
}

// round 7
// speedup vs baseline: 1.1850x; 1.0467x over previous
#include <cuda_runtime.h>
#include <cuda_bf16.h>

// EmbeddingSumConcat: out[b, f*E+e] = sum_{l < lengths[b,f]} tables[f, ids[b,f,l], e]
// B=4096, F=32, V=100000, L=20, E=64. ids/lengths int32 (JAX x64 disabled),
// tables/out fp32.
//
// R7: R3 kernel (best: 55.7us) with block=128 / grid=16384 (16 CTAs/SM, same
// 64 resident warps) for finer wave-tail granularity. evict_last hint dropped:
// unsupported encoding on v4.f32, and DRAM traffic is already at the
// compulsory floor so it couldn't cut volume anyway.

#define EB_B 4096
#define EB_F 32
#define EB_V 100000
#define EB_L 20
#define EB_E 64
#define EB_V4 (EB_E / 4)     // 16 float4 per row

__global__ __launch_bounds__(128, 16) void embbag_kernel(
    const int*    __restrict__ ids,      // int32 [B, F, L]
    const int*    __restrict__ lengths,  // int32 [B, F]
    const float4* __restrict__ tables,   // fp32  [F, V, E/4]
    float4*       __restrict__ out)      // fp32  [B, F, E/4]
{
    int tid = blockIdx.x * 128 + threadIdx.x;       // 0 .. B*F*16-1
    int v    = tid & (EB_V4 - 1);                   // float4 lane in row (0..15)
    int cell = tid >> 4;                            // f-major: cell = f*B + b
    int b    = cell & (EB_B - 1);                   // B = 4096 = 2^12
    int f    = cell >> 12;

    size_t bf = (size_t)b * EB_F + f;
    int n = lengths[bf];                            // 0..20
    const float4* base = tables + (size_t)f * EB_V * EB_V4;

    // Ids for this cell: 80 bytes, 16B-aligned (bf*80). 5x int4 loads,
    // hardware-broadcast across the 16 lanes of the cell.
    const int4* idp4 = (const int4*)(ids + bf * EB_L);
    int idbuf[EB_L];
#pragma unroll
    for (int q = 0; q < EB_L / 4; q++) {
        int4 w = __ldg(&idp4[q]);
        idbuf[q * 4 + 0] = w.x;
        idbuf[q * 4 + 1] = w.y;
        idbuf[q * 4 + 2] = w.z;
        idbuf[q * 4 + 3] = w.w;
    }

    float4 acc = make_float4(0.f, 0.f, 0.f, 0.f);
#pragma unroll
    for (int l = 0; l < EB_L; l++) {
        if (l < n) {
            float4 r = __ldg(&base[(size_t)idbuf[l] * EB_V4 + v]);
            acc.x += r.x; acc.y += r.y; acc.z += r.z; acc.w += r.w;
        }
    }

    // Streaming store: written once, never re-read; keep table rows in L2.
    __stcs(&out[bf * EB_V4 + v], acc);
}

extern "C" void kernel_launch(void* const* d_in, const int* in_sizes, int n_in,
                              void* d_out, int out_size) {
    const int*    ids     = (const int*)d_in[0];    // int32 [B,F,L]
    const int*    lengths = (const int*)d_in[1];    // int32 [B,F]
    const float4* tables  = (const float4*)d_in[2]; // fp32  [F,V,E]
    float4*       out     = (float4*)d_out;         // fp32  [B,F*E]

    int total = EB_B * EB_F * EB_V4;                // 2,097,152 threads
    embbag_kernel<<<total / 128, 128>>>(ids, lengths, tables, out);
}